// round 15
// baseline (speedup 1.0000x reference)
#include <cuda_runtime.h>
#include <cuda_fp16.h>
#include <cstdint>

// ---------------------------------------------------------------------------
// WaveletAttention: 3-level MODWT (db4 dilated circular convs) -> MHA
// B=4, L=2048, D=512, H=8, dh=64
// Round 15: H2-conv fused into vtrans (no vv round-trip) + deferred l-sum
//           shuffles; register-blocked convs + register-P 2-MMA attention
// ---------------------------------------------------------------------------

#define Bn  4
#define Ln  2048
#define Dn  512
#define Hn  8
#define NBD (Bn * Ln * Dn)   // 4,194,304

#define LAM 32.0f
#define C1  0.96875f    // 1 - 1/32
#define C2  0.03125f    // 1/32

__device__ float  g_v0[NBD];
__device__ float  g_v1[NBD];
__device__ float  g_v2[NBD];
__device__ float  g_q [NBD];
__device__ __half g_kh [NBD];   // K hi, [B][L][D]
__device__ __half g_kx [NBD];   // K X-form
__device__ __half g_vth[NBD];   // V^T hi, [B*H][64][L]
__device__ __half g_vtx[NBD];   // V^T X-form

// ---------------------------------------------------------------------------
__device__ __forceinline__ void split_x2(float x, float y,
                                         unsigned& hi, unsigned& xx) {
    __half hx = __float2half_rn(x);
    __half hy = __float2half_rn(y);
    float fx = __half2float(hx), fy = __half2float(hy);
    __half xxh = __float2half_rn(fx + LAM * (x - fx));
    __half xyh = __float2half_rn(fy + LAM * (y - fy));
    hi = ((unsigned)__half_as_ushort(hy) << 16) | __half_as_ushort(hx);
    xx = ((unsigned)__half_as_ushort(xyh) << 16) | __half_as_ushort(xxh);
}

__device__ __forceinline__ void mma_f16(float* c, const unsigned* a,
                                        unsigned b0, unsigned b1) {
    asm("mma.sync.aligned.m16n8k16.row.col.f32.f16.f16.f32 "
        "{%0,%1,%2,%3}, {%4,%5,%6,%7}, {%8,%9}, {%0,%1,%2,%3};"
        : "+f"(c[0]), "+f"(c[1]), "+f"(c[2]), "+f"(c[3])
        : "r"(a[0]), "r"(a[1]), "r"(a[2]), "r"(a[3]), "r"(b0), "r"(b1));
}

__device__ __forceinline__ float ex2f(float x) {
    float r;
    asm("ex2.approx.ftz.f32 %0, %1;" : "=f"(r) : "f"(x));
    return r;
}

__device__ __forceinline__ uint32_t s2u(const void* p) {
    uint32_t a;
    asm("{ .reg .u64 t; cvta.to.shared.u64 t, %1; cvt.u32.u64 %0, t; }"
        : "=r"(a) : "l"(p));
    return a;
}

#define CP_ASYNC16(daddr, src)                                                 \
    asm volatile("cp.async.cg.shared.global [%0], [%1], 16;"                   \
                 :: "r"(daddr), "l"(src))
#define CP_COMMIT()  asm volatile("cp.async.commit_group;" ::: "memory")
#define CP_WAIT0()   asm volatile("cp.async.wait_group 0;" ::: "memory")

#define FMA4(acc, t, v)                                                        \
    do { acc.x += (t) * (v).x; acc.y += (t) * (v).y;                           \
         acc.z += (t) * (v).z; acc.w += (t) * (v).w; } while (0)

// ---------------------------------------------------------------------------
// Register-blocked convs (round-14, validated): 4 t-positions/thread.
// ---------------------------------------------------------------------------
__global__ __launch_bounds__(256) void conv1_kernel(
    const float* __restrict__ in, float* __restrict__ out,
    const float* __restrict__ frow, int dil, int ldil)
{
    int idx = blockIdx.x * 256 + threadIdx.x;   // over NBD/16
    int d4 = idx & 127;
    int u  = (idx >> 7) & 511;
    int b  = idx >> 16;
    int base = (u & (dil - 1)) + ((u >> ldil) << (ldil + 2));

    const float* inb = in + ((long)b << 20) + (d4 << 2);
    float tap[8];
#pragma unroll
    for (int k = 0; k < 8; k++)
        tap[k] = __ldg(&frow[(Ln - dil * k) & (Ln - 1)]);

    float4 xv[11];
#pragma unroll
    for (int e = 0; e < 11; e++) {
        int src = (base + dil * (e - 7)) & (Ln - 1);
        xv[e] = *(const float4*)(inb + (src << 9));
    }

    float* ob = out + ((long)b << 20) + (d4 << 2);
#pragma unroll
    for (int j = 0; j < 4; j++) {
        float4 acc = {0.f, 0.f, 0.f, 0.f};
#pragma unroll
        for (int k = 0; k < 8; k++) FMA4(acc, tap[k], xv[7 + j - k]);
        int t = base + dil * j;
        *(float4*)(ob + ((long)t << 9)) = acc;
    }
}

__global__ __launch_bounds__(256) void conv2_kernel(
    const float* __restrict__ in,
    float* __restrict__ outA, const float* __restrict__ frowA,
    float* __restrict__ outB, const float* __restrict__ frowB,
    int dil, int ldil)
{
    int idx = blockIdx.x * 256 + threadIdx.x;
    int d4 = idx & 127;
    int u  = (idx >> 7) & 511;
    int b  = idx >> 16;
    int base = (u & (dil - 1)) + ((u >> ldil) << (ldil + 2));

    const float* inb = in + ((long)b << 20) + (d4 << 2);
    float tA[8], tB[8];
#pragma unroll
    for (int k = 0; k < 8; k++) {
        tA[k] = __ldg(&frowA[(Ln - dil * k) & (Ln - 1)]);
        tB[k] = __ldg(&frowB[(Ln - 2 * dil * k) & (Ln - 1)]);
    }

    float4 xv[18];
#pragma unroll
    for (int e = 0; e < 18; e++) {
        int src = (base + dil * (e - 14)) & (Ln - 1);
        xv[e] = *(const float4*)(inb + (src << 9));
    }

    float* oa = outA + ((long)b << 20) + (d4 << 2);
    float* ob = outB + ((long)b << 20) + (d4 << 2);
#pragma unroll
    for (int j = 0; j < 4; j++) {
        float4 aA = {0.f, 0.f, 0.f, 0.f};
        float4 aB = {0.f, 0.f, 0.f, 0.f};
#pragma unroll
        for (int k = 0; k < 8; k++) {
            FMA4(aA, tA[k], xv[14 + j - k]);
            FMA4(aB, tB[k], xv[14 + j - 2 * k]);
        }
        long off = ((long)(base + dil * j) << 9);
        *(float4*)(oa + off) = aA;
        *(float4*)(ob + off) = aB;
    }
}

__global__ __launch_bounds__(256) void conv2s_kernel(
    const float* __restrict__ in,
    __half* __restrict__ outAh, __half* __restrict__ outAx,
    const float* __restrict__ frowA,
    float* __restrict__ outB, const float* __restrict__ frowB,
    int dil, int ldil)
{
    int idx = blockIdx.x * 256 + threadIdx.x;
    int d4 = idx & 127;
    int u  = (idx >> 7) & 511;
    int b  = idx >> 16;
    int base = (u & (dil - 1)) + ((u >> ldil) << (ldil + 2));

    const float* inb = in + ((long)b << 20) + (d4 << 2);
    float tA[8], tB[8];
#pragma unroll
    for (int k = 0; k < 8; k++) {
        tA[k] = __ldg(&frowA[(Ln - dil * k) & (Ln - 1)]);
        tB[k] = __ldg(&frowB[(Ln - 2 * dil * k) & (Ln - 1)]);
    }

    float4 xv[18];
#pragma unroll
    for (int e = 0; e < 18; e++) {
        int src = (base + dil * (e - 14)) & (Ln - 1);
        xv[e] = *(const float4*)(inb + (src << 9));
    }

    __half* oah = outAh + ((long)b << 20) + (d4 << 2);
    __half* oax = outAx + ((long)b << 20) + (d4 << 2);
    float*  ob  = outB  + ((long)b << 20) + (d4 << 2);
#pragma unroll
    for (int j = 0; j < 4; j++) {
        float4 aA = {0.f, 0.f, 0.f, 0.f};
        float4 aB = {0.f, 0.f, 0.f, 0.f};
#pragma unroll
        for (int k = 0; k < 8; k++) {
            FMA4(aA, tA[k], xv[14 + j - k]);
            FMA4(aB, tB[k], xv[14 + j - 2 * k]);
        }
        long off = ((long)(base + dil * j) << 9);
        unsigned h01, x01, h23, x23;
        split_x2(aA.x, aA.y, h01, x01);
        split_x2(aA.z, aA.w, h23, x23);
        *(uint2*)(oah + off) = make_uint2(h01, h23);
        *(uint2*)(oax + off) = make_uint2(x01, x23);
        *(float4*)(ob + off) = aB;
    }
}

// ---------------------------------------------------------------------------
// Fused H2(dil=4) conv + transpose + split:
//   v2[b][t][h*64+dh] --H2--> vv --T--> vth/vtx[bh][dh][t]
// Block (t-tile 64, bh). smem: v2 tile with 28-row circular halo.
// ---------------------------------------------------------------------------
__global__ __launch_bounds__(256) void vtransf_kernel(
    const float* __restrict__ v2,
    __half* __restrict__ vth, __half* __restrict__ vtx,
    const float* __restrict__ wf)
{
    __shared__ float tile[92][65];
    const int t0 = blockIdx.x * 64;
    const int bh = blockIdx.y;
    const int b = bh >> 3, h = bh & 7;
    const int tid = threadIdx.x;
    const size_t LL = (size_t)Ln * Ln;

    float tH2[8];
#pragma unroll
    for (int k = 0; k < 8; k++)
        tH2[k] = __ldg(&wf[2 * LL + ((Ln - 4 * k) & (Ln - 1))]);

    const float* src = v2 + ((long)b << 20) + h * 64;
    for (int e = tid; e < 92 * 64; e += 256) {
        int r = e >> 6, c = e & 63;
        int t = (t0 - 28 + r) & (Ln - 1);
        tile[r][c] = src[((long)t << 9) + c];
    }
    __syncthreads();

    __half* dh_ = vth + (long)bh * 64 * Ln + t0;
    __half* dx_ = vtx + (long)bh * 64 * Ln + t0;
#pragma unroll
    for (int it = 0; it < 16; it++) {
        int o = it * 256 + tid;
        int key = o & 63, dh = o >> 6;
        float a = 0.f;
#pragma unroll
        for (int k = 0; k < 8; k++)
            a += tH2[k] * tile[key + 28 - 4 * k][dh];
        __half hi = __float2half_rn(a);
        float fh = __half2float(hi);
        __half xx = __float2half_rn(fh + LAM * (a - fh));
        dh_[(long)dh * Ln + key] = hi;
        dx_[(long)dh * Ln + key] = xx;
    }
}

// ---------------------------------------------------------------------------
// 2-MMA scaled-residual flash attention, register-resident P, exp2 softmax,
// DEFERRED l-sum reduction (exact reassociation; corr uniform per 4-group).
// ---------------------------------------------------------------------------
#define STRW 36
#define TILEW (64 * STRW)
#define BUFW  (4 * TILEW)
#define ASMEM (2 * BUFW * 4)   // 73728

#define QSCALE 0.18033688011112042f   // 0.125 * log2(e) -> exp2 domain

__global__ __launch_bounds__(256, 2) void attn_kernel(
    const float* __restrict__ Qg,
    const __half* __restrict__ Khg, const __half* __restrict__ Kxg,
    const __half* __restrict__ Vhg, const __half* __restrict__ Vxg,
    float* __restrict__ O)
{
    extern __shared__ unsigned sm_u[];
    const uint32_t sb = s2u(sm_u);

    const int tid = threadIdx.x;
    const int lane = tid & 31, warp = tid >> 5;
    const int g = lane >> 2, tg = lane & 3;
    const int bh = blockIdx.y;
    const int b = bh >> 3, h = bh & 7;
    const int q0 = blockIdx.x * 128;

    unsigned qah[4][4], qax[4][4];
    {
        const float* Qp = Qg + ((long)b * Ln + q0 + warp * 16) * Dn + h * 64;
#pragma unroll
        for (int kt = 0; kt < 4; kt++)
#pragma unroll
            for (int part = 0; part < 4; part++) {
                int row = g + (part & 1) * 8;
                int col = kt * 16 + ((part >> 1) << 3) + 2 * tg;
                float2 x = *(const float2*)(Qp + row * Dn + col);
                split_x2(x.x * QSCALE, x.y * QSCALE, qah[kt][part], qax[kt][part]);
            }
    }

    const __half* Kb  = Khg + (long)b * Ln * Dn + h * 64;
    const __half* Kxb = Kxg + (long)b * Ln * Dn + h * 64;
    const __half* Vb  = Vhg + (long)bh * 64 * Ln;
    const __half* Vxb = Vxg + (long)bh * 64 * Ln;

    auto issue_copy = [&](int tile, int bufsel) {
        const int k0 = tile * 64;
        const uint32_t bufbase = sb + (uint32_t)(bufsel * BUFW) * 4u;
#pragma unroll
        for (int j = 0; j < 8; j++) {
            int flat = j * 256 + tid;
            int arr = flat >> 9, rem = flat & 511;
            int row = rem >> 3, c = rem & 7;
            const __half* src;
            uint32_t doff;
            if (arr == 0)      { src = Kb  + (long)(k0 + row) * Dn + c * 8; doff = 0; }
            else if (arr == 1) { src = Kxb + (long)(k0 + row) * Dn + c * 8; doff = TILEW; }
            else if (arr == 2) { src = Vb  + (long)row * Ln + k0 + c * 8;   doff = 2 * TILEW; }
            else               { src = Vxb + (long)row * Ln + k0 + c * 8;   doff = 3 * TILEW; }
            uint32_t daddr = bufbase + (doff + row * STRW + c * 4) * 4u;
            CP_ASYNC16(daddr, src);
        }
        CP_COMMIT();
    };

    float m_[2] = {-1e30f, -1e30f}, l_[2] = {0.f, 0.f};  // l_: per-thread partial
    float oacc[8][4];
#pragma unroll
    for (int nt = 0; nt < 8; nt++)
#pragma unroll
        for (int j = 0; j < 4; j++) oacc[nt][j] = 0.f;

    issue_copy(0, 0);

    for (int it = 0; it < 32; it++) {
        CP_WAIT0();
        __syncthreads();
        if (it < 31) issue_copy(it + 1, (it + 1) & 1);

        unsigned* buf = sm_u + (it & 1) * BUFW;
        unsigned* sKh = buf;
        unsigned* sKx = buf + TILEW;
        unsigned* sVh = buf + 2 * TILEW;
        unsigned* sVx = buf + 3 * TILEW;

        // ---- S = Q K^T (2-MMA scheme)
        float sc[8][4];
#pragma unroll
        for (int nt = 0; nt < 8; nt++) {
            float ch[4] = {0.f, 0.f, 0.f, 0.f};
            float cx[4] = {0.f, 0.f, 0.f, 0.f};
            const unsigned* krh = sKh + (nt * 8 + g) * STRW;
            const unsigned* krx = sKx + (nt * 8 + g) * STRW;
#pragma unroll
            for (int kt = 0; kt < 4; kt++) {
                mma_f16(ch, qah[kt], krh[kt * 8 + tg], krh[kt * 8 + tg + 4]);
                mma_f16(cx, qax[kt], krx[kt * 8 + tg], krx[kt * 8 + tg + 4]);
            }
#pragma unroll
            for (int j = 0; j < 4; j++) sc[nt][j] = C1 * ch[j] + C2 * cx[j];
        }

        // ---- online softmax (exp2 domain), rows g, g+8
        float rmax[2] = {-1e30f, -1e30f};
#pragma unroll
        for (int nt = 0; nt < 8; nt++) {
            rmax[0] = fmaxf(rmax[0], fmaxf(sc[nt][0], sc[nt][1]));
            rmax[1] = fmaxf(rmax[1], fmaxf(sc[nt][2], sc[nt][3]));
        }
#pragma unroll
        for (int o = 1; o <= 2; o <<= 1) {
            rmax[0] = fmaxf(rmax[0], __shfl_xor_sync(0xffffffffu, rmax[0], o));
            rmax[1] = fmaxf(rmax[1], __shfl_xor_sync(0xffffffffu, rmax[1], o));
        }
        float corr[2];
#pragma unroll
        for (int r = 0; r < 2; r++) {
            float mn = fmaxf(m_[r], rmax[r]);
            corr[r] = ex2f(m_[r] - mn);
            m_[r] = mn;
        }

        unsigned ph01[8], ph23[8], px01[8], px23[8];
        float rsum[2] = {0.f, 0.f};
#pragma unroll
        for (int nt = 0; nt < 8; nt++) {
            float p0 = ex2f(sc[nt][0] - m_[0]);
            float p1 = ex2f(sc[nt][1] - m_[0]);
            float p2 = ex2f(sc[nt][2] - m_[1]);
            float p3 = ex2f(sc[nt][3] - m_[1]);
            rsum[0] += p0 + p1; rsum[1] += p2 + p3;
            split_x2(p0, p1, ph01[nt], px01[nt]);
            split_x2(p2, p3, ph23[nt], px23[nt]);
        }
        // deferred: no shuffle here — per-thread partial l only
        l_[0] = l_[0] * corr[0] + rsum[0];
        l_[1] = l_[1] * corr[1] + rsum[1];
#pragma unroll
        for (int nt = 0; nt < 8; nt++) {
            oacc[nt][0] *= corr[0]; oacc[nt][1] *= corr[0];
            oacc[nt][2] *= corr[1]; oacc[nt][3] *= corr[1];
        }

        // ---- O += P V (P A-fragments straight from registers)
#pragma unroll
        for (int nt = 0; nt < 8; nt++) {
            float ch[4] = {0.f, 0.f, 0.f, 0.f};
            float cx[4] = {0.f, 0.f, 0.f, 0.f};
            const unsigned* vrh = sVh + (nt * 8 + g) * STRW;
            const unsigned* vrx = sVx + (nt * 8 + g) * STRW;
#pragma unroll
            for (int kt = 0; kt < 4; kt++) {
                unsigned pah[4] = {ph01[2 * kt], ph23[2 * kt],
                                   ph01[2 * kt + 1], ph23[2 * kt + 1]};
                unsigned pax[4] = {px01[2 * kt], px23[2 * kt],
                                   px01[2 * kt + 1], px23[2 * kt + 1]};
                mma_f16(ch, pah, vrh[kt * 8 + tg], vrh[kt * 8 + tg + 4]);
                mma_f16(cx, pax, vrx[kt * 8 + tg], vrx[kt * 8 + tg + 4]);
            }
#pragma unroll
            for (int j = 0; j < 4; j++)
                oacc[nt][j] += C1 * ch[j] + C2 * cx[j];
        }
    }

    // ---- final cross-thread l reduction (4-thread groups share a row)
#pragma unroll
    for (int o = 1; o <= 2; o <<= 1) {
        l_[0] += __shfl_xor_sync(0xffffffffu, l_[0], o);
        l_[1] += __shfl_xor_sync(0xffffffffu, l_[1], o);
    }

    // ---- epilogue
    float inv0 = 1.f / l_[0], inv1 = 1.f / l_[1];
    long row0 = (long)b * Ln + q0 + warp * 16 + g;
    long row1 = row0 + 8;
#pragma unroll
    for (int nt = 0; nt < 8; nt++) {
        int col = h * 64 + nt * 8 + 2 * tg;
        float2 v0 = {oacc[nt][0] * inv0, oacc[nt][1] * inv0};
        float2 v1 = {oacc[nt][2] * inv1, oacc[nt][3] * inv1};
        *(float2*)(O + row0 * Dn + col) = v0;
        *(float2*)(O + row1 * Dn + col) = v1;
    }
}

// ---------------------------------------------------------------------------
extern "C" void kernel_launch(void* const* d_in, const int* in_sizes, int n_in,
                              void* d_out, int out_size)
{
    const float* x  = (const float*)d_in[0];
    const float* vf = (const float*)d_in[1];
    const float* wf = (const float*)d_in[2];
    float* out = (float*)d_out;

    float *v0, *v1, *v2, *q;
    __half *kh, *kx, *vth, *vtx;
    cudaGetSymbolAddress((void**)&v0,  g_v0);
    cudaGetSymbolAddress((void**)&v1,  g_v1);
    cudaGetSymbolAddress((void**)&v2,  g_v2);
    cudaGetSymbolAddress((void**)&q,   g_q);
    cudaGetSymbolAddress((void**)&kh,  g_kh);
    cudaGetSymbolAddress((void**)&kx,  g_kx);
    cudaGetSymbolAddress((void**)&vth, g_vth);
    cudaGetSymbolAddress((void**)&vtx, g_vtx);

    const size_t LL = (size_t)Ln * Ln;
    const int cblocks = (NBD / 16) / 256;   // 1024

    // v0 = L0(x); {q = H0(v0), v1 = L1(v0)}; {k = H1(v1), v2 = L2(v1)};
    // V^T = T(H2(v2)) fused into vtransf
    conv1_kernel<<<cblocks, 256>>>(x, v0, vf, 1, 0);
    conv2_kernel<<<cblocks, 256>>>(v0, q, wf, v1, vf + LL, 1, 0);
    conv2s_kernel<<<cblocks, 256>>>(v1, kh, kx, wf + LL, v2, vf + 2 * LL, 2, 1);
    vtransf_kernel<<<dim3(Ln / 64, Bn * Hn), 256>>>(v2, vth, vtx, wf);

    cudaFuncSetAttribute(attn_kernel,
                         cudaFuncAttributeMaxDynamicSharedMemorySize, ASMEM);
    dim3 grid(Ln / 128, Bn * Hn);   // (16, 32)
    attn_kernel<<<grid, 256, ASMEM>>>(q, kh, kx, vth, vtx, out);
}

// round 16
// speedup vs baseline: 1.0060x; 1.0060x over previous
#include <cuda_runtime.h>
#include <cuda_fp16.h>
#include <cstdint>

// ---------------------------------------------------------------------------
// WaveletAttention: 3-level MODWT (db4 dilated circular convs) -> MHA
// B=4, L=2048, D=512, H=8, dh=64
// Round 16: round-14 attention (best measured) + 128-row fused H2+transpose
// ---------------------------------------------------------------------------

#define Bn  4
#define Ln  2048
#define Dn  512
#define Hn  8
#define NBD (Bn * Ln * Dn)   // 4,194,304

#define LAM 32.0f
#define C1  0.96875f    // 1 - 1/32
#define C2  0.03125f    // 1/32

__device__ float  g_v0[NBD];
__device__ float  g_v1[NBD];
__device__ float  g_v2[NBD];
__device__ float  g_q [NBD];
__device__ __half g_kh [NBD];   // K hi, [B][L][D]
__device__ __half g_kx [NBD];   // K X-form
__device__ __half g_vth[NBD];   // V^T hi, [B*H][64][L]
__device__ __half g_vtx[NBD];   // V^T X-form

// ---------------------------------------------------------------------------
__device__ __forceinline__ void split_x2(float x, float y,
                                         unsigned& hi, unsigned& xx) {
    __half hx = __float2half_rn(x);
    __half hy = __float2half_rn(y);
    float fx = __half2float(hx), fy = __half2float(hy);
    __half xxh = __float2half_rn(fx + LAM * (x - fx));
    __half xyh = __float2half_rn(fy + LAM * (y - fy));
    hi = ((unsigned)__half_as_ushort(hy) << 16) | __half_as_ushort(hx);
    xx = ((unsigned)__half_as_ushort(xyh) << 16) | __half_as_ushort(xxh);
}

__device__ __forceinline__ void mma_f16(float* c, const unsigned* a,
                                        unsigned b0, unsigned b1) {
    asm("mma.sync.aligned.m16n8k16.row.col.f32.f16.f16.f32 "
        "{%0,%1,%2,%3}, {%4,%5,%6,%7}, {%8,%9}, {%0,%1,%2,%3};"
        : "+f"(c[0]), "+f"(c[1]), "+f"(c[2]), "+f"(c[3])
        : "r"(a[0]), "r"(a[1]), "r"(a[2]), "r"(a[3]), "r"(b0), "r"(b1));
}

__device__ __forceinline__ float ex2f(float x) {
    float r;
    asm("ex2.approx.ftz.f32 %0, %1;" : "=f"(r) : "f"(x));
    return r;
}

__device__ __forceinline__ uint32_t s2u(const void* p) {
    uint32_t a;
    asm("{ .reg .u64 t; cvta.to.shared.u64 t, %1; cvt.u32.u64 %0, t; }"
        : "=r"(a) : "l"(p));
    return a;
}

#define CP_ASYNC16(daddr, src)                                                 \
    asm volatile("cp.async.cg.shared.global [%0], [%1], 16;"                   \
                 :: "r"(daddr), "l"(src))
#define CP_COMMIT()  asm volatile("cp.async.commit_group;" ::: "memory")
#define CP_WAIT0()   asm volatile("cp.async.wait_group 0;" ::: "memory")

#define FMA4(acc, t, v)                                                        \
    do { acc.x += (t) * (v).x; acc.y += (t) * (v).y;                           \
         acc.z += (t) * (v).z; acc.w += (t) * (v).w; } while (0)

// ---------------------------------------------------------------------------
// Register-blocked convs (round-14, validated): 4 t-positions/thread.
// ---------------------------------------------------------------------------
__global__ __launch_bounds__(256) void conv1_kernel(
    const float* __restrict__ in, float* __restrict__ out,
    const float* __restrict__ frow, int dil, int ldil)
{
    int idx = blockIdx.x * 256 + threadIdx.x;   // over NBD/16
    int d4 = idx & 127;
    int u  = (idx >> 7) & 511;
    int b  = idx >> 16;
    int base = (u & (dil - 1)) + ((u >> ldil) << (ldil + 2));

    const float* inb = in + ((long)b << 20) + (d4 << 2);
    float tap[8];
#pragma unroll
    for (int k = 0; k < 8; k++)
        tap[k] = __ldg(&frow[(Ln - dil * k) & (Ln - 1)]);

    float4 xv[11];
#pragma unroll
    for (int e = 0; e < 11; e++) {
        int src = (base + dil * (e - 7)) & (Ln - 1);
        xv[e] = *(const float4*)(inb + (src << 9));
    }

    float* ob = out + ((long)b << 20) + (d4 << 2);
#pragma unroll
    for (int j = 0; j < 4; j++) {
        float4 acc = {0.f, 0.f, 0.f, 0.f};
#pragma unroll
        for (int k = 0; k < 8; k++) FMA4(acc, tap[k], xv[7 + j - k]);
        int t = base + dil * j;
        *(float4*)(ob + ((long)t << 9)) = acc;
    }
}

__global__ __launch_bounds__(256) void conv2_kernel(
    const float* __restrict__ in,
    float* __restrict__ outA, const float* __restrict__ frowA,
    float* __restrict__ outB, const float* __restrict__ frowB,
    int dil, int ldil)
{
    int idx = blockIdx.x * 256 + threadIdx.x;
    int d4 = idx & 127;
    int u  = (idx >> 7) & 511;
    int b  = idx >> 16;
    int base = (u & (dil - 1)) + ((u >> ldil) << (ldil + 2));

    const float* inb = in + ((long)b << 20) + (d4 << 2);
    float tA[8], tB[8];
#pragma unroll
    for (int k = 0; k < 8; k++) {
        tA[k] = __ldg(&frowA[(Ln - dil * k) & (Ln - 1)]);
        tB[k] = __ldg(&frowB[(Ln - 2 * dil * k) & (Ln - 1)]);
    }

    float4 xv[18];
#pragma unroll
    for (int e = 0; e < 18; e++) {
        int src = (base + dil * (e - 14)) & (Ln - 1);
        xv[e] = *(const float4*)(inb + (src << 9));
    }

    float* oa = outA + ((long)b << 20) + (d4 << 2);
    float* ob = outB + ((long)b << 20) + (d4 << 2);
#pragma unroll
    for (int j = 0; j < 4; j++) {
        float4 aA = {0.f, 0.f, 0.f, 0.f};
        float4 aB = {0.f, 0.f, 0.f, 0.f};
#pragma unroll
        for (int k = 0; k < 8; k++) {
            FMA4(aA, tA[k], xv[14 + j - k]);
            FMA4(aB, tB[k], xv[14 + j - 2 * k]);
        }
        long off = ((long)(base + dil * j) << 9);
        *(float4*)(oa + off) = aA;
        *(float4*)(ob + off) = aB;
    }
}

__global__ __launch_bounds__(256) void conv2s_kernel(
    const float* __restrict__ in,
    __half* __restrict__ outAh, __half* __restrict__ outAx,
    const float* __restrict__ frowA,
    float* __restrict__ outB, const float* __restrict__ frowB,
    int dil, int ldil)
{
    int idx = blockIdx.x * 256 + threadIdx.x;
    int d4 = idx & 127;
    int u  = (idx >> 7) & 511;
    int b  = idx >> 16;
    int base = (u & (dil - 1)) + ((u >> ldil) << (ldil + 2));

    const float* inb = in + ((long)b << 20) + (d4 << 2);
    float tA[8], tB[8];
#pragma unroll
    for (int k = 0; k < 8; k++) {
        tA[k] = __ldg(&frowA[(Ln - dil * k) & (Ln - 1)]);
        tB[k] = __ldg(&frowB[(Ln - 2 * dil * k) & (Ln - 1)]);
    }

    float4 xv[18];
#pragma unroll
    for (int e = 0; e < 18; e++) {
        int src = (base + dil * (e - 14)) & (Ln - 1);
        xv[e] = *(const float4*)(inb + (src << 9));
    }

    __half* oah = outAh + ((long)b << 20) + (d4 << 2);
    __half* oax = outAx + ((long)b << 20) + (d4 << 2);
    float*  ob  = outB  + ((long)b << 20) + (d4 << 2);
#pragma unroll
    for (int j = 0; j < 4; j++) {
        float4 aA = {0.f, 0.f, 0.f, 0.f};
        float4 aB = {0.f, 0.f, 0.f, 0.f};
#pragma unroll
        for (int k = 0; k < 8; k++) {
            FMA4(aA, tA[k], xv[14 + j - k]);
            FMA4(aB, tB[k], xv[14 + j - 2 * k]);
        }
        long off = ((long)(base + dil * j) << 9);
        unsigned h01, x01, h23, x23;
        split_x2(aA.x, aA.y, h01, x01);
        split_x2(aA.z, aA.w, h23, x23);
        *(uint2*)(oah + off) = make_uint2(h01, h23);
        *(uint2*)(oax + off) = make_uint2(x01, x23);
        *(float4*)(ob + off) = aB;
    }
}

// ---------------------------------------------------------------------------
// Fused H2(dil=4) conv + transpose + split, 128-row t-tiles (halo 1.22x):
//   v2[b][t][h*64+dh] --H2--> vv --T--> vth/vtx[bh][dh][t]
// Block (t-tile 128, bh). smem tile[156][65] = 40,560 B.
// ---------------------------------------------------------------------------
#define VT_SMEM (156 * 65 * 4)

__global__ __launch_bounds__(256) void vtransf_kernel(
    const float* __restrict__ v2,
    __half* __restrict__ vth, __half* __restrict__ vtx,
    const float* __restrict__ wf)
{
    extern __shared__ float tile_[];
    float (*tile)[65] = (float(*)[65])tile_;
    const int t0 = blockIdx.x * 128;
    const int bh = blockIdx.y;
    const int b = bh >> 3, h = bh & 7;
    const int tid = threadIdx.x;
    const size_t LL = (size_t)Ln * Ln;

    float tH2[8];
#pragma unroll
    for (int k = 0; k < 8; k++)
        tH2[k] = __ldg(&wf[2 * LL + ((Ln - 4 * k) & (Ln - 1))]);

    const float* src = v2 + ((long)b << 20) + h * 64;
    for (int e = tid; e < 156 * 64; e += 256) {
        int r = e >> 6, c = e & 63;
        int t = (t0 - 28 + r) & (Ln - 1);
        tile[r][c] = src[((long)t << 9) + c];
    }
    __syncthreads();

    __half* dh_ = vth + (long)bh * 64 * Ln + t0;
    __half* dx_ = vtx + (long)bh * 64 * Ln + t0;
#pragma unroll
    for (int it = 0; it < 32; it++) {
        int o = it * 256 + tid;
        int key = o & 127, dh = o >> 7;
        float a = 0.f;
#pragma unroll
        for (int k = 0; k < 8; k++)
            a += tH2[k] * tile[key + 28 - 4 * k][dh];
        __half hi = __float2half_rn(a);
        float fh = __half2float(hi);
        __half xx = __float2half_rn(fh + LAM * (a - fh));
        dh_[(long)dh * Ln + key] = hi;
        dx_[(long)dh * Ln + key] = xx;
    }
}

// ---------------------------------------------------------------------------
// 2-MMA scaled-residual flash attention, register-resident P, exp2 softmax.
// (round-14 kernel, restored verbatim — best measured)
// ---------------------------------------------------------------------------
#define STRW 36
#define TILEW (64 * STRW)
#define BUFW  (4 * TILEW)
#define ASMEM (2 * BUFW * 4)   // 73728

#define QSCALE 0.18033688011112042f   // 0.125 * log2(e) -> exp2 domain

__global__ __launch_bounds__(256, 2) void attn_kernel(
    const float* __restrict__ Qg,
    const __half* __restrict__ Khg, const __half* __restrict__ Kxg,
    const __half* __restrict__ Vhg, const __half* __restrict__ Vxg,
    float* __restrict__ O)
{
    extern __shared__ unsigned sm_u[];
    const uint32_t sb = s2u(sm_u);

    const int tid = threadIdx.x;
    const int lane = tid & 31, warp = tid >> 5;
    const int g = lane >> 2, tg = lane & 3;
    const int bh = blockIdx.y;
    const int b = bh >> 3, h = bh & 7;
    const int q0 = blockIdx.x * 128;

    unsigned qah[4][4], qax[4][4];
    {
        const float* Qp = Qg + ((long)b * Ln + q0 + warp * 16) * Dn + h * 64;
#pragma unroll
        for (int kt = 0; kt < 4; kt++)
#pragma unroll
            for (int part = 0; part < 4; part++) {
                int row = g + (part & 1) * 8;
                int col = kt * 16 + ((part >> 1) << 3) + 2 * tg;
                float2 x = *(const float2*)(Qp + row * Dn + col);
                split_x2(x.x * QSCALE, x.y * QSCALE, qah[kt][part], qax[kt][part]);
            }
    }

    const __half* Kb  = Khg + (long)b * Ln * Dn + h * 64;
    const __half* Kxb = Kxg + (long)b * Ln * Dn + h * 64;
    const __half* Vb  = Vhg + (long)bh * 64 * Ln;
    const __half* Vxb = Vxg + (long)bh * 64 * Ln;

    auto issue_copy = [&](int tile, int bufsel) {
        const int k0 = tile * 64;
        const uint32_t bufbase = sb + (uint32_t)(bufsel * BUFW) * 4u;
#pragma unroll
        for (int j = 0; j < 8; j++) {
            int flat = j * 256 + tid;
            int arr = flat >> 9, rem = flat & 511;
            int row = rem >> 3, c = rem & 7;
            const __half* src;
            uint32_t doff;
            if (arr == 0)      { src = Kb  + (long)(k0 + row) * Dn + c * 8; doff = 0; }
            else if (arr == 1) { src = Kxb + (long)(k0 + row) * Dn + c * 8; doff = TILEW; }
            else if (arr == 2) { src = Vb  + (long)row * Ln + k0 + c * 8;   doff = 2 * TILEW; }
            else               { src = Vxb + (long)row * Ln + k0 + c * 8;   doff = 3 * TILEW; }
            uint32_t daddr = bufbase + (doff + row * STRW + c * 4) * 4u;
            CP_ASYNC16(daddr, src);
        }
        CP_COMMIT();
    };

    float m_[2] = {-1e30f, -1e30f}, l_[2] = {0.f, 0.f};
    float oacc[8][4];
#pragma unroll
    for (int nt = 0; nt < 8; nt++)
#pragma unroll
        for (int j = 0; j < 4; j++) oacc[nt][j] = 0.f;

    issue_copy(0, 0);

    for (int it = 0; it < 32; it++) {
        CP_WAIT0();
        __syncthreads();
        if (it < 31) issue_copy(it + 1, (it + 1) & 1);

        unsigned* buf = sm_u + (it & 1) * BUFW;
        unsigned* sKh = buf;
        unsigned* sKx = buf + TILEW;
        unsigned* sVh = buf + 2 * TILEW;
        unsigned* sVx = buf + 3 * TILEW;

        // ---- S = Q K^T (2-MMA scheme)
        float sc[8][4];
#pragma unroll
        for (int nt = 0; nt < 8; nt++) {
            float ch[4] = {0.f, 0.f, 0.f, 0.f};
            float cx[4] = {0.f, 0.f, 0.f, 0.f};
            const unsigned* krh = sKh + (nt * 8 + g) * STRW;
            const unsigned* krx = sKx + (nt * 8 + g) * STRW;
#pragma unroll
            for (int kt = 0; kt < 4; kt++) {
                mma_f16(ch, qah[kt], krh[kt * 8 + tg], krh[kt * 8 + tg + 4]);
                mma_f16(cx, qax[kt], krx[kt * 8 + tg], krx[kt * 8 + tg + 4]);
            }
#pragma unroll
            for (int j = 0; j < 4; j++) sc[nt][j] = C1 * ch[j] + C2 * cx[j];
        }

        // ---- online softmax (exp2 domain), rows g, g+8
        float rmax[2] = {-1e30f, -1e30f};
#pragma unroll
        for (int nt = 0; nt < 8; nt++) {
            rmax[0] = fmaxf(rmax[0], fmaxf(sc[nt][0], sc[nt][1]));
            rmax[1] = fmaxf(rmax[1], fmaxf(sc[nt][2], sc[nt][3]));
        }
#pragma unroll
        for (int o = 1; o <= 2; o <<= 1) {
            rmax[0] = fmaxf(rmax[0], __shfl_xor_sync(0xffffffffu, rmax[0], o));
            rmax[1] = fmaxf(rmax[1], __shfl_xor_sync(0xffffffffu, rmax[1], o));
        }
        float corr[2];
#pragma unroll
        for (int r = 0; r < 2; r++) {
            float mn = fmaxf(m_[r], rmax[r]);
            corr[r] = ex2f(m_[r] - mn);
            m_[r] = mn;
        }

        unsigned ph01[8], ph23[8], px01[8], px23[8];
        float rsum[2] = {0.f, 0.f};
#pragma unroll
        for (int nt = 0; nt < 8; nt++) {
            float p0 = ex2f(sc[nt][0] - m_[0]);
            float p1 = ex2f(sc[nt][1] - m_[0]);
            float p2 = ex2f(sc[nt][2] - m_[1]);
            float p3 = ex2f(sc[nt][3] - m_[1]);
            rsum[0] += p0 + p1; rsum[1] += p2 + p3;
            split_x2(p0, p1, ph01[nt], px01[nt]);
            split_x2(p2, p3, ph23[nt], px23[nt]);
        }
#pragma unroll
        for (int o = 1; o <= 2; o <<= 1) {
            rsum[0] += __shfl_xor_sync(0xffffffffu, rsum[0], o);
            rsum[1] += __shfl_xor_sync(0xffffffffu, rsum[1], o);
        }
        l_[0] = l_[0] * corr[0] + rsum[0];
        l_[1] = l_[1] * corr[1] + rsum[1];
#pragma unroll
        for (int nt = 0; nt < 8; nt++) {
            oacc[nt][0] *= corr[0]; oacc[nt][1] *= corr[0];
            oacc[nt][2] *= corr[1]; oacc[nt][3] *= corr[1];
        }

        // ---- O += P V (P A-fragments straight from registers)
#pragma unroll
        for (int nt = 0; nt < 8; nt++) {
            float ch[4] = {0.f, 0.f, 0.f, 0.f};
            float cx[4] = {0.f, 0.f, 0.f, 0.f};
            const unsigned* vrh = sVh + (nt * 8 + g) * STRW;
            const unsigned* vrx = sVx + (nt * 8 + g) * STRW;
#pragma unroll
            for (int kt = 0; kt < 4; kt++) {
                unsigned pah[4] = {ph01[2 * kt], ph23[2 * kt],
                                   ph01[2 * kt + 1], ph23[2 * kt + 1]};
                unsigned pax[4] = {px01[2 * kt], px23[2 * kt],
                                   px01[2 * kt + 1], px23[2 * kt + 1]};
                mma_f16(ch, pah, vrh[kt * 8 + tg], vrh[kt * 8 + tg + 4]);
                mma_f16(cx, pax, vrx[kt * 8 + tg], vrx[kt * 8 + tg + 4]);
            }
#pragma unroll
            for (int j = 0; j < 4; j++)
                oacc[nt][j] += C1 * ch[j] + C2 * cx[j];
        }
    }

    // ---- epilogue
    float inv0 = 1.f / l_[0], inv1 = 1.f / l_[1];
    long row0 = (long)b * Ln + q0 + warp * 16 + g;
    long row1 = row0 + 8;
#pragma unroll
    for (int nt = 0; nt < 8; nt++) {
        int col = h * 64 + nt * 8 + 2 * tg;
        float2 v0 = {oacc[nt][0] * inv0, oacc[nt][1] * inv0};
        float2 v1 = {oacc[nt][2] * inv1, oacc[nt][3] * inv1};
        *(float2*)(O + row0 * Dn + col) = v0;
        *(float2*)(O + row1 * Dn + col) = v1;
    }
}

// ---------------------------------------------------------------------------
extern "C" void kernel_launch(void* const* d_in, const int* in_sizes, int n_in,
                              void* d_out, int out_size)
{
    const float* x  = (const float*)d_in[0];
    const float* vf = (const float*)d_in[1];
    const float* wf = (const float*)d_in[2];
    float* out = (float*)d_out;

    float *v0, *v1, *v2, *q;
    __half *kh, *kx, *vth, *vtx;
    cudaGetSymbolAddress((void**)&v0,  g_v0);
    cudaGetSymbolAddress((void**)&v1,  g_v1);
    cudaGetSymbolAddress((void**)&v2,  g_v2);
    cudaGetSymbolAddress((void**)&q,   g_q);
    cudaGetSymbolAddress((void**)&kh,  g_kh);
    cudaGetSymbolAddress((void**)&kx,  g_kx);
    cudaGetSymbolAddress((void**)&vth, g_vth);
    cudaGetSymbolAddress((void**)&vtx, g_vtx);

    const size_t LL = (size_t)Ln * Ln;
    const int cblocks = (NBD / 16) / 256;   // 1024

    // v0 = L0(x); {q = H0(v0), v1 = L1(v0)}; {k = H1(v1), v2 = L2(v1)};
    // V^T = T(H2(v2)) fused into vtransf (128-row tiles)
    conv1_kernel<<<cblocks, 256>>>(x, v0, vf, 1, 0);
    conv2_kernel<<<cblocks, 256>>>(v0, q, wf, v1, vf + LL, 1, 0);
    conv2s_kernel<<<cblocks, 256>>>(v1, kh, kx, wf + LL, v2, vf + 2 * LL, 2, 1);

    cudaFuncSetAttribute(vtransf_kernel,
                         cudaFuncAttributeMaxDynamicSharedMemorySize, VT_SMEM);
    vtransf_kernel<<<dim3(Ln / 128, Bn * Hn), 256, VT_SMEM>>>(v2, vth, vtx, wf);

    cudaFuncSetAttribute(attn_kernel,
                         cudaFuncAttributeMaxDynamicSharedMemorySize, ASMEM);
    dim3 grid(Ln / 128, Bn * Hn);   // (16, 32)
    attn_kernel<<<grid, 256, ASMEM>>>(q, kh, kx, vth, vtx, out);
}

// round 17
// speedup vs baseline: 1.0253x; 1.0192x over previous
#include <cuda_runtime.h>
#include <cuda_fp16.h>
#include <cstdint>

// ---------------------------------------------------------------------------
// WaveletAttention: 3-level MODWT (db4 dilated circular convs) -> MHA
// B=4, L=2048, D=512, H=8, dh=64
// Round 17: composite-filter fused conv12 (x -> q,v1; no v0 pass)
//           + round-14 conv2s + round-15 vtransf(64) + round-14 attention
// ---------------------------------------------------------------------------

#define Bn  4
#define Ln  2048
#define Dn  512
#define Hn  8
#define NBD (Bn * Ln * Dn)   // 4,194,304

#define LAM 32.0f
#define C1  0.96875f    // 1 - 1/32
#define C2  0.03125f    // 1/32

__device__ float  g_v1 [NBD];
__device__ float  g_v2 [NBD];
__device__ float  g_q  [NBD];
__device__ __half g_kh [NBD];   // K hi, [B][L][D]
__device__ __half g_kx [NBD];   // K X-form
__device__ __half g_vth[NBD];   // V^T hi, [B*H][64][L]
__device__ __half g_vtx[NBD];   // V^T X-form

// ---------------------------------------------------------------------------
__device__ __forceinline__ void split_x2(float x, float y,
                                         unsigned& hi, unsigned& xx) {
    __half hx = __float2half_rn(x);
    __half hy = __float2half_rn(y);
    float fx = __half2float(hx), fy = __half2float(hy);
    __half xxh = __float2half_rn(fx + LAM * (x - fx));
    __half xyh = __float2half_rn(fy + LAM * (y - fy));
    hi = ((unsigned)__half_as_ushort(hy) << 16) | __half_as_ushort(hx);
    xx = ((unsigned)__half_as_ushort(xyh) << 16) | __half_as_ushort(xxh);
}

__device__ __forceinline__ void mma_f16(float* c, const unsigned* a,
                                        unsigned b0, unsigned b1) {
    asm("mma.sync.aligned.m16n8k16.row.col.f32.f16.f16.f32 "
        "{%0,%1,%2,%3}, {%4,%5,%6,%7}, {%8,%9}, {%0,%1,%2,%3};"
        : "+f"(c[0]), "+f"(c[1]), "+f"(c[2]), "+f"(c[3])
        : "r"(a[0]), "r"(a[1]), "r"(a[2]), "r"(a[3]), "r"(b0), "r"(b1));
}

__device__ __forceinline__ float ex2f(float x) {
    float r;
    asm("ex2.approx.ftz.f32 %0, %1;" : "=f"(r) : "f"(x));
    return r;
}

__device__ __forceinline__ uint32_t s2u(const void* p) {
    uint32_t a;
    asm("{ .reg .u64 t; cvta.to.shared.u64 t, %1; cvt.u32.u64 %0, t; }"
        : "=r"(a) : "l"(p));
    return a;
}

#define CP_ASYNC16(daddr, src)                                                 \
    asm volatile("cp.async.cg.shared.global [%0], [%1], 16;"                   \
                 :: "r"(daddr), "l"(src))
#define CP_COMMIT()  asm volatile("cp.async.commit_group;" ::: "memory")
#define CP_WAIT0()   asm volatile("cp.async.wait_group 0;" ::: "memory")

#define FMA4(acc, t, v)                                                        \
    do { acc.x += (t) * (v).x; acc.y += (t) * (v).y;                           \
         acc.z += (t) * (v).z; acc.w += (t) * (v).w; } while (0)

// ---------------------------------------------------------------------------
// Fused conv12: x -> { q = (H0*L0)(x) [15 taps], v1 = (L1^2 * L0)(x) [22 taps] }
// Composite taps computed once per block into smem. 4 t/thread, load-major.
// ---------------------------------------------------------------------------
__global__ __launch_bounds__(256) void conv12_kernel(
    const float* __restrict__ x, float* __restrict__ q, float* __restrict__ v1,
    const float* __restrict__ vf, const float* __restrict__ wf)
{
    __shared__ float stq[15], stv[22];
    const int tid = threadIdx.x;
    const size_t LL = (size_t)Ln * Ln;

    if (tid < 15) {
        float a = 0.f;
#pragma unroll
        for (int j = 0; j <= 7; j++) {
            int k = tid - j;
            if (k >= 0 && k <= 7)
                a += __ldg(&wf[(Ln - j) & (Ln - 1)]) *
                     __ldg(&vf[(Ln - k) & (Ln - 1)]);
        }
        stq[tid] = a;
    } else if (tid >= 32 && tid < 54) {
        int m = tid - 32;
        float a = 0.f;
#pragma unroll
        for (int j = 0; j <= 7; j++) {
            int k = m - 2 * j;
            if (k >= 0 && k <= 7)
                a += __ldg(&vf[LL + ((Ln - 2 * j) & (Ln - 1))]) *
                     __ldg(&vf[(Ln - k) & (Ln - 1)]);
        }
        stv[m] = a;
    }
    __syncthreads();

    float tqr[15], tvr[22];
#pragma unroll
    for (int m = 0; m < 15; m++) tqr[m] = stq[m];
#pragma unroll
    for (int m = 0; m < 22; m++) tvr[m] = stv[m];

    int idx = blockIdx.x * 256 + tid;    // over NBD/16
    int d4 = idx & 127;
    int u  = (idx >> 7) & 511;
    int b  = idx >> 16;
    int base = u * 4;

    const float* inb = x + ((long)b << 20) + (d4 << 2);
    float4 aq[4], av[4];
#pragma unroll
    for (int j = 0; j < 4; j++) {
        aq[j] = make_float4(0.f, 0.f, 0.f, 0.f);
        av[j] = make_float4(0.f, 0.f, 0.f, 0.f);
    }

#pragma unroll
    for (int o = -21; o <= 3; o++) {
        int src = (base + o) & (Ln - 1);
        float4 xv = *(const float4*)(inb + (src << 9));
#pragma unroll
        for (int j = 0; j < 4; j++) {
            int m = j - o;
            if (m >= 0 && m <= 14) FMA4(aq[j], tqr[m], xv);
            if (m >= 0 && m <= 21) FMA4(av[j], tvr[m], xv);
        }
    }

    float* qb = q  + ((long)b << 20) + (d4 << 2);
    float* vb = v1 + ((long)b << 20) + (d4 << 2);
#pragma unroll
    for (int j = 0; j < 4; j++) {
        long off = ((long)(base + j) << 9);
        *(float4*)(qb + off) = aq[j];
        *(float4*)(vb + off) = av[j];
    }
}

// ---------------------------------------------------------------------------
// conv2s (round-14): v1 -> { K hi/X (dil 2), v2 (dil 4) }, 4 t/thread
// ---------------------------------------------------------------------------
__global__ __launch_bounds__(256) void conv2s_kernel(
    const float* __restrict__ in,
    __half* __restrict__ outAh, __half* __restrict__ outAx,
    const float* __restrict__ frowA,
    float* __restrict__ outB, const float* __restrict__ frowB,
    int dil, int ldil)
{
    int idx = blockIdx.x * 256 + threadIdx.x;
    int d4 = idx & 127;
    int u  = (idx >> 7) & 511;
    int b  = idx >> 16;
    int base = (u & (dil - 1)) + ((u >> ldil) << (ldil + 2));

    const float* inb = in + ((long)b << 20) + (d4 << 2);
    float tA[8], tB[8];
#pragma unroll
    for (int k = 0; k < 8; k++) {
        tA[k] = __ldg(&frowA[(Ln - dil * k) & (Ln - 1)]);
        tB[k] = __ldg(&frowB[(Ln - 2 * dil * k) & (Ln - 1)]);
    }

    float4 xv[18];
#pragma unroll
    for (int e = 0; e < 18; e++) {
        int src = (base + dil * (e - 14)) & (Ln - 1);
        xv[e] = *(const float4*)(inb + (src << 9));
    }

    __half* oah = outAh + ((long)b << 20) + (d4 << 2);
    __half* oax = outAx + ((long)b << 20) + (d4 << 2);
    float*  ob  = outB  + ((long)b << 20) + (d4 << 2);
#pragma unroll
    for (int j = 0; j < 4; j++) {
        float4 aA = {0.f, 0.f, 0.f, 0.f};
        float4 aB = {0.f, 0.f, 0.f, 0.f};
#pragma unroll
        for (int k = 0; k < 8; k++) {
            FMA4(aA, tA[k], xv[14 + j - k]);
            FMA4(aB, tB[k], xv[14 + j - 2 * k]);
        }
        long off = ((long)(base + dil * j) << 9);
        unsigned h01, x01, h23, x23;
        split_x2(aA.x, aA.y, h01, x01);
        split_x2(aA.z, aA.w, h23, x23);
        *(uint2*)(oah + off) = make_uint2(h01, h23);
        *(uint2*)(oax + off) = make_uint2(x01, x23);
        *(float4*)(ob + off) = aB;
    }
}

// ---------------------------------------------------------------------------
// Fused H2(dil=4) conv + transpose + split, 64-row t-tiles (round-15 version)
// ---------------------------------------------------------------------------
__global__ __launch_bounds__(256) void vtransf_kernel(
    const float* __restrict__ v2,
    __half* __restrict__ vth, __half* __restrict__ vtx,
    const float* __restrict__ wf)
{
    __shared__ float tile[92][65];
    const int t0 = blockIdx.x * 64;
    const int bh = blockIdx.y;
    const int b = bh >> 3, h = bh & 7;
    const int tid = threadIdx.x;
    const size_t LL = (size_t)Ln * Ln;

    float tH2[8];
#pragma unroll
    for (int k = 0; k < 8; k++)
        tH2[k] = __ldg(&wf[2 * LL + ((Ln - 4 * k) & (Ln - 1))]);

    const float* src = v2 + ((long)b << 20) + h * 64;
    for (int e = tid; e < 92 * 64; e += 256) {
        int r = e >> 6, c = e & 63;
        int t = (t0 - 28 + r) & (Ln - 1);
        tile[r][c] = src[((long)t << 9) + c];
    }
    __syncthreads();

    __half* dh_ = vth + (long)bh * 64 * Ln + t0;
    __half* dx_ = vtx + (long)bh * 64 * Ln + t0;
#pragma unroll
    for (int it = 0; it < 16; it++) {
        int o = it * 256 + tid;
        int key = o & 63, dh = o >> 6;
        float a = 0.f;
#pragma unroll
        for (int k = 0; k < 8; k++)
            a += tH2[k] * tile[key + 28 - 4 * k][dh];
        __half hi = __float2half_rn(a);
        float fh = __half2float(hi);
        __half xx = __float2half_rn(fh + LAM * (a - fh));
        dh_[(long)dh * Ln + key] = hi;
        dx_[(long)dh * Ln + key] = xx;
    }
}

// ---------------------------------------------------------------------------
// 2-MMA scaled-residual flash attention, register-resident P, exp2 softmax.
// (round-14 kernel, unchanged — at its mma.sync structural floor)
// ---------------------------------------------------------------------------
#define STRW 36
#define TILEW (64 * STRW)
#define BUFW  (4 * TILEW)
#define ASMEM (2 * BUFW * 4)   // 73728

#define QSCALE 0.18033688011112042f   // 0.125 * log2(e) -> exp2 domain

__global__ __launch_bounds__(256, 2) void attn_kernel(
    const float* __restrict__ Qg,
    const __half* __restrict__ Khg, const __half* __restrict__ Kxg,
    const __half* __restrict__ Vhg, const __half* __restrict__ Vxg,
    float* __restrict__ O)
{
    extern __shared__ unsigned sm_u[];
    const uint32_t sb = s2u(sm_u);

    const int tid = threadIdx.x;
    const int lane = tid & 31, warp = tid >> 5;
    const int g = lane >> 2, tg = lane & 3;
    const int bh = blockIdx.y;
    const int b = bh >> 3, h = bh & 7;
    const int q0 = blockIdx.x * 128;

    unsigned qah[4][4], qax[4][4];
    {
        const float* Qp = Qg + ((long)b * Ln + q0 + warp * 16) * Dn + h * 64;
#pragma unroll
        for (int kt = 0; kt < 4; kt++)
#pragma unroll
            for (int part = 0; part < 4; part++) {
                int row = g + (part & 1) * 8;
                int col = kt * 16 + ((part >> 1) << 3) + 2 * tg;
                float2 x = *(const float2*)(Qp + row * Dn + col);
                split_x2(x.x * QSCALE, x.y * QSCALE, qah[kt][part], qax[kt][part]);
            }
    }

    const __half* Kb  = Khg + (long)b * Ln * Dn + h * 64;
    const __half* Kxb = Kxg + (long)b * Ln * Dn + h * 64;
    const __half* Vb  = Vhg + (long)bh * 64 * Ln;
    const __half* Vxb = Vxg + (long)bh * 64 * Ln;

    auto issue_copy = [&](int tile, int bufsel) {
        const int k0 = tile * 64;
        const uint32_t bufbase = sb + (uint32_t)(bufsel * BUFW) * 4u;
#pragma unroll
        for (int j = 0; j < 8; j++) {
            int flat = j * 256 + tid;
            int arr = flat >> 9, rem = flat & 511;
            int row = rem >> 3, c = rem & 7;
            const __half* src;
            uint32_t doff;
            if (arr == 0)      { src = Kb  + (long)(k0 + row) * Dn + c * 8; doff = 0; }
            else if (arr == 1) { src = Kxb + (long)(k0 + row) * Dn + c * 8; doff = TILEW; }
            else if (arr == 2) { src = Vb  + (long)row * Ln + k0 + c * 8;   doff = 2 * TILEW; }
            else               { src = Vxb + (long)row * Ln + k0 + c * 8;   doff = 3 * TILEW; }
            uint32_t daddr = bufbase + (doff + row * STRW + c * 4) * 4u;
            CP_ASYNC16(daddr, src);
        }
        CP_COMMIT();
    };

    float m_[2] = {-1e30f, -1e30f}, l_[2] = {0.f, 0.f};
    float oacc[8][4];
#pragma unroll
    for (int nt = 0; nt < 8; nt++)
#pragma unroll
        for (int j = 0; j < 4; j++) oacc[nt][j] = 0.f;

    issue_copy(0, 0);

    for (int it = 0; it < 32; it++) {
        CP_WAIT0();
        __syncthreads();
        if (it < 31) issue_copy(it + 1, (it + 1) & 1);

        unsigned* buf = sm_u + (it & 1) * BUFW;
        unsigned* sKh = buf;
        unsigned* sKx = buf + TILEW;
        unsigned* sVh = buf + 2 * TILEW;
        unsigned* sVx = buf + 3 * TILEW;

        float sc[8][4];
#pragma unroll
        for (int nt = 0; nt < 8; nt++) {
            float ch[4] = {0.f, 0.f, 0.f, 0.f};
            float cx[4] = {0.f, 0.f, 0.f, 0.f};
            const unsigned* krh = sKh + (nt * 8 + g) * STRW;
            const unsigned* krx = sKx + (nt * 8 + g) * STRW;
#pragma unroll
            for (int kt = 0; kt < 4; kt++) {
                mma_f16(ch, qah[kt], krh[kt * 8 + tg], krh[kt * 8 + tg + 4]);
                mma_f16(cx, qax[kt], krx[kt * 8 + tg], krx[kt * 8 + tg + 4]);
            }
#pragma unroll
            for (int j = 0; j < 4; j++) sc[nt][j] = C1 * ch[j] + C2 * cx[j];
        }

        float rmax[2] = {-1e30f, -1e30f};
#pragma unroll
        for (int nt = 0; nt < 8; nt++) {
            rmax[0] = fmaxf(rmax[0], fmaxf(sc[nt][0], sc[nt][1]));
            rmax[1] = fmaxf(rmax[1], fmaxf(sc[nt][2], sc[nt][3]));
        }
#pragma unroll
        for (int o = 1; o <= 2; o <<= 1) {
            rmax[0] = fmaxf(rmax[0], __shfl_xor_sync(0xffffffffu, rmax[0], o));
            rmax[1] = fmaxf(rmax[1], __shfl_xor_sync(0xffffffffu, rmax[1], o));
        }
        float corr[2];
#pragma unroll
        for (int r = 0; r < 2; r++) {
            float mn = fmaxf(m_[r], rmax[r]);
            corr[r] = ex2f(m_[r] - mn);
            m_[r] = mn;
        }

        unsigned ph01[8], ph23[8], px01[8], px23[8];
        float rsum[2] = {0.f, 0.f};
#pragma unroll
        for (int nt = 0; nt < 8; nt++) {
            float p0 = ex2f(sc[nt][0] - m_[0]);
            float p1 = ex2f(sc[nt][1] - m_[0]);
            float p2 = ex2f(sc[nt][2] - m_[1]);
            float p3 = ex2f(sc[nt][3] - m_[1]);
            rsum[0] += p0 + p1; rsum[1] += p2 + p3;
            split_x2(p0, p1, ph01[nt], px01[nt]);
            split_x2(p2, p3, ph23[nt], px23[nt]);
        }
#pragma unroll
        for (int o = 1; o <= 2; o <<= 1) {
            rsum[0] += __shfl_xor_sync(0xffffffffu, rsum[0], o);
            rsum[1] += __shfl_xor_sync(0xffffffffu, rsum[1], o);
        }
        l_[0] = l_[0] * corr[0] + rsum[0];
        l_[1] = l_[1] * corr[1] + rsum[1];
#pragma unroll
        for (int nt = 0; nt < 8; nt++) {
            oacc[nt][0] *= corr[0]; oacc[nt][1] *= corr[0];
            oacc[nt][2] *= corr[1]; oacc[nt][3] *= corr[1];
        }

#pragma unroll
        for (int nt = 0; nt < 8; nt++) {
            float ch[4] = {0.f, 0.f, 0.f, 0.f};
            float cx[4] = {0.f, 0.f, 0.f, 0.f};
            const unsigned* vrh = sVh + (nt * 8 + g) * STRW;
            const unsigned* vrx = sVx + (nt * 8 + g) * STRW;
#pragma unroll
            for (int kt = 0; kt < 4; kt++) {
                unsigned pah[4] = {ph01[2 * kt], ph23[2 * kt],
                                   ph01[2 * kt + 1], ph23[2 * kt + 1]};
                unsigned pax[4] = {px01[2 * kt], px23[2 * kt],
                                   px01[2 * kt + 1], px23[2 * kt + 1]};
                mma_f16(ch, pah, vrh[kt * 8 + tg], vrh[kt * 8 + tg + 4]);
                mma_f16(cx, pax, vrx[kt * 8 + tg], vrx[kt * 8 + tg + 4]);
            }
#pragma unroll
            for (int j = 0; j < 4; j++)
                oacc[nt][j] += C1 * ch[j] + C2 * cx[j];
        }
    }

    float inv0 = 1.f / l_[0], inv1 = 1.f / l_[1];
    long row0 = (long)b * Ln + q0 + warp * 16 + g;
    long row1 = row0 + 8;
#pragma unroll
    for (int nt = 0; nt < 8; nt++) {
        int col = h * 64 + nt * 8 + 2 * tg;
        float2 v0 = {oacc[nt][0] * inv0, oacc[nt][1] * inv0};
        float2 v1 = {oacc[nt][2] * inv1, oacc[nt][3] * inv1};
        *(float2*)(O + row0 * Dn + col) = v0;
        *(float2*)(O + row1 * Dn + col) = v1;
    }
}

// ---------------------------------------------------------------------------
extern "C" void kernel_launch(void* const* d_in, const int* in_sizes, int n_in,
                              void* d_out, int out_size)
{
    const float* x  = (const float*)d_in[0];
    const float* vf = (const float*)d_in[1];
    const float* wf = (const float*)d_in[2];
    float* out = (float*)d_out;

    float *v1, *v2, *q;
    __half *kh, *kx, *vth, *vtx;
    cudaGetSymbolAddress((void**)&v1,  g_v1);
    cudaGetSymbolAddress((void**)&v2,  g_v2);
    cudaGetSymbolAddress((void**)&q,   g_q);
    cudaGetSymbolAddress((void**)&kh,  g_kh);
    cudaGetSymbolAddress((void**)&kx,  g_kx);
    cudaGetSymbolAddress((void**)&vth, g_vth);
    cudaGetSymbolAddress((void**)&vtx, g_vtx);

    const size_t LL = (size_t)Ln * Ln;
    const int cblocks = (NBD / 16) / 256;   // 1024

    // {q, v1} = composite(x);  {K hi/X, v2} = conv2s(v1);  V^T = vtransf(v2)
    conv12_kernel<<<cblocks, 256>>>(x, q, v1, vf, wf);
    conv2s_kernel<<<cblocks, 256>>>(v1, kh, kx, wf + LL, v2, vf + 2 * LL, 2, 1);
    vtransf_kernel<<<dim3(Ln / 64, Bn * Hn), 256>>>(v2, vth, vtx, wf);

    cudaFuncSetAttribute(attn_kernel,
                         cudaFuncAttributeMaxDynamicSharedMemorySize, ASMEM);
    dim3 grid(Ln / 128, Bn * Hn);   // (16, 32)
    attn_kernel<<<grid, 256, ASMEM>>>(q, kh, kx, vth, vtx, out);
}